// round 6
// baseline (speedup 1.0000x reference)
#include <cuda_runtime.h>
#include <cstdint>

// Householder reflection per row, B=8192, L=4096, fp32.
//   out[b,:] = z[b,:] - 2 * v[b,:] * (v.z)/(v.v)
//
// One CTA per row (grid=8192, 256 threads). ALL global traffic on the async
// proxy: cp.async.bulk loads v,z into smem (R5 win: bypasses the cross-CTA
// L1tex wavefront queue), and the output is computed in-place into the z
// smem region then written with a single cp.async.bulk store — per-thread
// STG eliminated so stores no longer contend in the LSU queue either.

constexpr int THREADS = 256;
constexpr int L       = 4096;
constexpr int L4      = L / 4;             // 1024 float4 per row
constexpr int PER     = L4 / THREADS;      // 4 float4 per thread per tensor
constexpr int ROW_BYTES   = L * 4;         // 16384
constexpr int STAGE_BYTES = 2 * ROW_BYTES; // 32768 (v + z)

__device__ __forceinline__ uint32_t smem_u32(const void* p) {
    return (uint32_t)__cvta_generic_to_shared(p);
}

__global__ __launch_bounds__(THREADS)
void hh_tma2_kernel(const float4* __restrict__ v,
                    const float4* __restrict__ z,
                    float4* __restrict__ out)
{
    extern __shared__ float4 sm[];            // v: [0,1024), z/out: [1024,2048)
    __shared__ __align__(8) unsigned long long mbar;
    __shared__ float s_part[16];              // 8 warps x {vz, vv}
    __shared__ float s_scale;

    const int t    = threadIdx.x;
    const int lane = t & 31;
    const int wid  = t >> 5;
    const size_t base = (size_t)blockIdx.x * L4;

    const uint32_t mb = smem_u32(&mbar);

    if (t == 0) {
        asm volatile("mbarrier.init.shared::cta.b64 [%0], %1;"
                     :: "r"(mb), "r"(1));
        asm volatile("fence.proxy.async.shared::cta;" ::: "memory");
    }
    __syncthreads();

    if (t == 0) {
        asm volatile("mbarrier.arrive.expect_tx.shared::cta.b64 _, [%0], %1;"
                     :: "r"(mb), "r"(STAGE_BYTES) : "memory");
        asm volatile("cp.async.bulk.shared::cta.global.mbarrier::complete_tx::bytes"
                     " [%0], [%1], %2, [%3];"
                     :: "r"(smem_u32(sm)), "l"(v + base), "r"(ROW_BYTES), "r"(mb)
                     : "memory");
        asm volatile("cp.async.bulk.shared::cta.global.mbarrier::complete_tx::bytes"
                     " [%0], [%1], %2, [%3];"
                     :: "r"(smem_u32(sm + L4)), "l"(z + base), "r"(ROW_BYTES), "r"(mb)
                     : "memory");
    }

    // Wait (parity 0, single-shot barrier), acquire for generic smem reads
    {
        uint32_t done;
        asm volatile(
            "{\n\t.reg .pred p;\n\t"
            "mbarrier.try_wait.parity.acquire.cta.shared::cta.b64 p, [%1], %2;\n\t"
            "selp.b32 %0, 1, 0, p;\n\t}"
            : "=r"(done) : "r"(mb), "r"(0) : "memory");
        while (!done) {
            asm volatile(
                "{\n\t.reg .pred p;\n\t"
                "mbarrier.try_wait.parity.acquire.cta.shared::cta.b64 p, [%1], %2, 0x989680;\n\t"
                "selp.b32 %0, 1, 0, p;\n\t}"
                : "=r"(done) : "r"(mb), "r"(0) : "memory");
        }
    }

    // Dot pass from smem
    float dvz = 0.0f, dvv = 0.0f;
    #pragma unroll
    for (int i = 0; i < PER; i++) {
        const float4 a = sm[t + i * THREADS];
        const float4 b = sm[L4 + t + i * THREADS];
        dvz += a.x * b.x + a.y * b.y + a.z * b.z + a.w * b.w;
        dvv += a.x * a.x + a.y * a.y + a.z * a.z + a.w * a.w;
    }

    #pragma unroll
    for (int off = 16; off > 0; off >>= 1) {
        dvz += __shfl_xor_sync(0xFFFFFFFFu, dvz, off);
        dvv += __shfl_xor_sync(0xFFFFFFFFu, dvv, off);
    }
    if (lane == 0) { s_part[wid] = dvz; s_part[8 + wid] = dvv; }
    __syncthreads();

    if (wid == 0) {
        float a = (lane < 8) ? s_part[lane] : 0.0f;
        float c = (lane < 8) ? s_part[8 + lane] : 0.0f;
        #pragma unroll
        for (int off = 4; off > 0; off >>= 1) {
            a += __shfl_xor_sync(0xFFFFFFFFu, a, off);
            c += __shfl_xor_sync(0xFFFFFFFFu, c, off);
        }
        if (lane == 0) s_scale = 2.0f * a / c;
    }
    __syncthreads();

    const float scale = s_scale;

    // Output pass: compute o = z - scale*v in-place into the z smem region
    #pragma unroll
    for (int i = 0; i < PER; i++) {
        const float4 a = sm[t + i * THREADS];
        float4 b = sm[L4 + t + i * THREADS];
        b.x -= scale * a.x;
        b.y -= scale * a.y;
        b.z -= scale * a.z;
        b.w -= scale * a.w;
        sm[L4 + t + i * THREADS] = b;
    }

    __syncthreads();                                  // all STS visible
    if (t == 0) {
        asm volatile("fence.proxy.async.shared::cta;" ::: "memory");
        asm volatile("cp.async.bulk.global.shared::cta.bulk_group"
                     " [%0], [%1], %2;"
                     :: "l"(out + base), "r"(smem_u32(sm + L4)), "r"(ROW_BYTES)
                     : "memory");
        asm volatile("cp.async.bulk.commit_group;" ::: "memory");
        asm volatile("cp.async.bulk.wait_group 0;" ::: "memory");
    }
}

extern "C" void kernel_launch(void* const* d_in, const int* in_sizes, int n_in,
                              void* d_out, int out_size)
{
    const float4* v = (const float4*)d_in[0];
    const float4* z = (const float4*)d_in[1];
    float4* out = (float4*)d_out;

    const int B = in_sizes[0] / L;    // 8192

    static bool attr_set = false;
    if (!attr_set) {
        cudaFuncSetAttribute(hh_tma2_kernel,
                             cudaFuncAttributeMaxDynamicSharedMemorySize,
                             STAGE_BYTES);
        attr_set = true;
    }

    hh_tma2_kernel<<<B, THREADS, STAGE_BYTES>>>(v, z, out);
}

// round 7
// speedup vs baseline: 1.1442x; 1.1442x over previous
#include <cuda_runtime.h>
#include <cstdint>

// Householder reflection per row, B=8192, L=4096, fp32.
//   out[b,:] = z[b,:] - 2 * v[b,:] * (v.z)/(v.v)
//
// R5 base (best: 62.4us, DRAM 83%): one CTA per row, cp.async.bulk loads
// into smem (bypasses cross-CTA L1tex queue contention), per-thread __stcs
// stores (R6 showed TMA stores regress).
// R7 change: single smem pass — rv/rz captured into registers during the
// dot pass, output computed from registers. Halves LDS traffic and shortens
// the post-mbarrier critical path.

constexpr int THREADS = 256;
constexpr int L       = 4096;
constexpr int L4      = L / 4;             // 1024 float4 per row
constexpr int PER     = L4 / THREADS;      // 4 float4 per thread per tensor
constexpr int ROW_BYTES   = L * 4;         // 16384
constexpr int STAGE_BYTES = 2 * ROW_BYTES; // 32768 (v + z)

__device__ __forceinline__ uint32_t smem_u32(const void* p) {
    return (uint32_t)__cvta_generic_to_shared(p);
}

__global__ __launch_bounds__(THREADS)
void hh_tma_r7_kernel(const float4* __restrict__ v,
                      const float4* __restrict__ z,
                      float4* __restrict__ out)
{
    extern __shared__ float4 sm[];            // v: [0,1024), z: [1024,2048)
    __shared__ __align__(8) unsigned long long mbar;
    __shared__ float s_part[16];              // 8 warps x {vz, vv}
    __shared__ float s_scale;

    const int t    = threadIdx.x;
    const int lane = t & 31;
    const int wid  = t >> 5;
    const size_t base = (size_t)blockIdx.x * L4;

    const uint32_t mb = smem_u32(&mbar);

    if (t == 0) {
        asm volatile("mbarrier.init.shared::cta.b64 [%0], %1;"
                     :: "r"(mb), "r"(1));
        asm volatile("fence.proxy.async.shared::cta;" ::: "memory");
    }
    __syncthreads();

    if (t == 0) {
        asm volatile("mbarrier.arrive.expect_tx.shared::cta.b64 _, [%0], %1;"
                     :: "r"(mb), "r"(STAGE_BYTES) : "memory");
        asm volatile("cp.async.bulk.shared::cta.global.mbarrier::complete_tx::bytes"
                     " [%0], [%1], %2, [%3];"
                     :: "r"(smem_u32(sm)), "l"(v + base), "r"(ROW_BYTES), "r"(mb)
                     : "memory");
        asm volatile("cp.async.bulk.shared::cta.global.mbarrier::complete_tx::bytes"
                     " [%0], [%1], %2, [%3];"
                     :: "r"(smem_u32(sm + L4)), "l"(z + base), "r"(ROW_BYTES), "r"(mb)
                     : "memory");
    }

    // Wait (parity 0, single-shot barrier), acquire for generic smem reads
    {
        uint32_t done;
        asm volatile(
            "{\n\t.reg .pred p;\n\t"
            "mbarrier.try_wait.parity.acquire.cta.shared::cta.b64 p, [%1], %2;\n\t"
            "selp.b32 %0, 1, 0, p;\n\t}"
            : "=r"(done) : "r"(mb), "r"(0) : "memory");
        while (!done) {
            asm volatile(
                "{\n\t.reg .pred p;\n\t"
                "mbarrier.try_wait.parity.acquire.cta.shared::cta.b64 p, [%1], %2, 0x989680;\n\t"
                "selp.b32 %0, 1, 0, p;\n\t}"
                : "=r"(done) : "r"(mb), "r"(0) : "memory");
        }
    }

    // Single smem pass: capture payload in registers, accumulate both dots
    float4 rv[PER], rz[PER];
    float dvz = 0.0f, dvv = 0.0f;
    #pragma unroll
    for (int i = 0; i < PER; i++) {
        rv[i] = sm[t + i * THREADS];
        rz[i] = sm[L4 + t + i * THREADS];
        dvz += rv[i].x * rz[i].x + rv[i].y * rz[i].y
             + rv[i].z * rz[i].z + rv[i].w * rz[i].w;
        dvv += rv[i].x * rv[i].x + rv[i].y * rv[i].y
             + rv[i].z * rv[i].z + rv[i].w * rv[i].w;
    }

    #pragma unroll
    for (int off = 16; off > 0; off >>= 1) {
        dvz += __shfl_xor_sync(0xFFFFFFFFu, dvz, off);
        dvv += __shfl_xor_sync(0xFFFFFFFFu, dvv, off);
    }
    if (lane == 0) { s_part[wid] = dvz; s_part[8 + wid] = dvv; }
    __syncthreads();

    if (wid == 0) {
        float a = (lane < 8) ? s_part[lane] : 0.0f;
        float c = (lane < 8) ? s_part[8 + lane] : 0.0f;
        #pragma unroll
        for (int off = 4; off > 0; off >>= 1) {
            a += __shfl_xor_sync(0xFFFFFFFFu, a, off);
            c += __shfl_xor_sync(0xFFFFFFFFu, c, off);
        }
        if (lane == 0) s_scale = 2.0f * a / c;
    }
    __syncthreads();

    const float nscale = -s_scale;
    float4* og = out + base;

    // Output from registers: o = z + (-scale) * v, streaming stores
    #pragma unroll
    for (int i = 0; i < PER; i++) {
        float4 o;
        o.x = fmaf(nscale, rv[i].x, rz[i].x);
        o.y = fmaf(nscale, rv[i].y, rz[i].y);
        o.z = fmaf(nscale, rv[i].z, rz[i].z);
        o.w = fmaf(nscale, rv[i].w, rz[i].w);
        __stcs(og + t + i * THREADS, o);
    }
}

extern "C" void kernel_launch(void* const* d_in, const int* in_sizes, int n_in,
                              void* d_out, int out_size)
{
    const float4* v = (const float4*)d_in[0];
    const float4* z = (const float4*)d_in[1];
    float4* out = (float4*)d_out;

    const int B = in_sizes[0] / L;    // 8192

    static bool attr_set = false;
    if (!attr_set) {
        cudaFuncSetAttribute(hh_tma_r7_kernel,
                             cudaFuncAttributeMaxDynamicSharedMemorySize,
                             STAGE_BYTES);
        attr_set = true;
    }

    hh_tma_r7_kernel<<<B, THREADS, STAGE_BYTES>>>(v, z, out);
}